// round 2
// baseline (speedup 1.0000x reference)
#include <cuda_runtime.h>
#include <cuda_bf16.h>
#include <cstdint>

// ConvPooler — per-token dot(h[b,s,:], w) + bias scattered into
// out[b, gene_pos[b,s]] over a [B, 60000] zeroed buffer; pad id 60000 dropped.
// B=32, S=2048, D=512, FULL_SEQ_LEN=60000.

#define B_DIM 32
#define S_DIM 2048
#define D_DIM 512
#define FULL_SEQ 60000

// ---------------------------------------------------------------------------
// Kernel 1: zero the output buffer (vectorized float4 grid-stride).
// out_size = 32*60000 = 1,920,000 floats, divisible by 4.
// ---------------------------------------------------------------------------
__global__ void zero_out_kernel(float4* __restrict__ out, int n4) {
    int i = blockIdx.x * blockDim.x + threadIdx.x;
    int stride = gridDim.x * blockDim.x;
    float4 z = make_float4(0.f, 0.f, 0.f, 0.f);
    for (; i < n4; i += stride) out[i] = z;
}

// ---------------------------------------------------------------------------
// Kernel 2: one warp per token. D=512 floats -> each of 32 lanes loads
// 4 float4 (16 floats), FMA vs w, warp shfl-reduce, lane 0 scatters.
// gene_pos is int32 (JAX without x64 demotes int64 -> int32).
// ---------------------------------------------------------------------------
__global__ __launch_bounds__(256, 8)
void conv_scatter_kernel(const float4* __restrict__ h,        // [B*S, D/4]
                         const int* __restrict__ gene_pos,    // [B*S] int32
                         const float4* __restrict__ w,        // [D/4]
                         const float* __restrict__ bias,      // [1]
                         float* __restrict__ out) {           // [B, FULL_SEQ]
    const int warp_id = (blockIdx.x * blockDim.x + threadIdx.x) >> 5;
    const int lane    = threadIdx.x & 31;
    const int n_tok   = B_DIM * S_DIM;
    if (warp_id >= n_tok) return;

    // Each token row: 512 floats = 128 float4. Lane pattern:
    // iter j in [0,4): index lane + 32*j -> fully coalesced 128B per iter.
    const float4* hrow = h + (size_t)warp_id * (D_DIM / 4);

    float acc = 0.f;
#pragma unroll
    for (int j = 0; j < 4; ++j) {
        const int idx = lane + 32 * j;
        float4 hv = hrow[idx];
        float4 wv = __ldg(&w[idx]);   // broadcast; L1-resident after first touch
        acc = fmaf(hv.x, wv.x, acc);
        acc = fmaf(hv.y, wv.y, acc);
        acc = fmaf(hv.z, wv.z, acc);
        acc = fmaf(hv.w, wv.w, acc);
    }

    // butterfly reduction across the warp
#pragma unroll
    for (int off = 16; off > 0; off >>= 1)
        acc += __shfl_xor_sync(0xFFFFFFFFu, acc, off);

    if (lane == 0) {
        int gp = gene_pos[warp_id];
        if (gp >= 0 && gp < FULL_SEQ) {   // pad id == FULL_SEQ dropped; guard OOB
            int row = warp_id / S_DIM;    // batch index (S_DIM power of 2 -> shift)
            out[(size_t)row * FULL_SEQ + (size_t)gp] = acc + bias[0];
        }
    }
}

// ---------------------------------------------------------------------------
// Launch — map inputs by element count, not position, to be robust to
// metadata ordering: h=33554432, gene_pos=65536, w=512, b=1.
// ---------------------------------------------------------------------------
extern "C" void kernel_launch(void* const* d_in, const int* in_sizes, int n_in,
                              void* d_out, int out_size) {
    const void* h_p = nullptr;
    const void* gp_p = nullptr;
    const void* w_p = nullptr;
    const void* b_p = nullptr;
    for (int i = 0; i < n_in; ++i) {
        switch (in_sizes[i]) {
            case B_DIM * S_DIM * D_DIM: h_p  = d_in[i]; break;  // 33,554,432
            case B_DIM * S_DIM:         gp_p = d_in[i]; break;  // 65,536
            case D_DIM:                 w_p  = d_in[i]; break;  // 512
            case 1:                     b_p  = d_in[i]; break;
            default: break;
        }
    }

    const float* h  = (const float*)h_p;
    const int*   gp = (const int*)gp_p;
    const float* w  = (const float*)w_p;
    const float* b  = (const float*)b_p;
    float* out = (float*)d_out;

    // Zero the output (out_size = 1,920,000, divisible by 4).
    int n4 = out_size / 4;
    int zt = 256;
    int zb = (n4 + zt - 1) / zt;
    if (zb > 4736) zb = 4736;  // cap; grid-stride covers the rest
    zero_out_kernel<<<zb, zt>>>((float4*)out, n4);

    // One warp per token: 65536 warps, 8 per block -> 8192 blocks.
    const int n_tok = B_DIM * S_DIM;
    const int threads = 256;
    const int blocks = (n_tok * 32) / threads;  // 8192
    conv_scatter_kernel<<<blocks, threads>>>(
        (const float4*)h, gp, (const float4*)w, b, out);
}